// round 11
// baseline (speedup 1.0000x reference)
#include <cuda_runtime.h>

// ProjectionSimToPointCloud: image (2048, 8192, 4) f32 -> points (2048*8192, 3) f32
//   depth = image[..., 3]
//   pitch(i) = (1 - i/h) * (FOV_UP + |FOV_DOWN|) - |FOV_DOWN|
//   yaw(j)   = j/w * 2*pi - pi
//   x = depth*cos(yaw), y = -depth*sin(yaw), z = depth*sin(pitch)
//
// Persistent grid-stride version of R10 (best: 68.5us kernel):
//  - 1024 CTAs x 256 thr, 16 iterations each; iteration pixel-stride =
//    1,048,576 px = exactly 128 rows -> j (yaw) is iteration-invariant:
//    __sincosf computed ONCE per thread, reused 16x
//  - 4x fully-coalesced LDG.128 + 3x STG.128 per iteration (same pattern
//    as R10); loop lets ptxas pipeline loads across iterations
//  - per-iteration cost: 1 warp-uniform __sinf + 12 FMUL + index adds

#define IMG_H   2048
#define IMG_W   8192
#define PPT     4                      // pixels per thread per iteration
#define GRID    1024
#define BLOCK   256
#define NT      (GRID * BLOCK)         // 262144 threads
#define ITERS   ((IMG_H * IMG_W) / PPT / NT)   // 16
#define ROWSTEP ((NT * PPT) >> 13)     // rows advanced per iteration = 128

__global__ void __launch_bounds__(BLOCK) project_persist(
    const float4* __restrict__ img,   // (H*W) float4 pixels, .w = depth
    float* __restrict__ out)          // (H*W*3) floats
{
    const int t  = blockIdx.x * blockDim.x + threadIdx.x;
    const int p0 = t * PPT;                 // first pixel of iteration 0
    const int j0 = p0 & (IMG_W - 1);        // column: invariant across iterations
    const int i0 = p0 >> 13;                // starting row

    // Yaw trig: once per thread, reused every iteration.
    const float YAW_STEP = 7.6699039394282161e-4f;   // 2*pi/8192
    const float PI_F     = 3.14159265358979323846f;
    const float yaw0 = (float)j0 * YAW_STEP - PI_F;
    float s0, c0, s1, c1, s2, c2, s3, c3;
    __sincosf(yaw0,                  &s0, &c0);
    __sincosf(yaw0 + 1.f * YAW_STEP, &s1, &c1);
    __sincosf(yaw0 + 2.f * YAW_STEP, &s2, &c2);
    __sincosf(yaw0 + 3.f * YAW_STEP, &s3, &c3);

    const float PITCH_A = 0.26179938779914943654f;   // FOV_UP in radians
    const float PITCH_B = 2.5566346454293863e-4f;    // (30deg in rad)/2048

    #pragma unroll 4
    for (int k = 0; k < ITERS; k++) {
        const int p = p0 + k * (NT * PPT);           // pixel base this iteration
        const int i = i0 + k * ROWSTEP;              // row this iteration

        // 4 independent fully-coalesced LDG.128, front-batched.
        const float4 v0 = img[p + 0];
        const float4 v1 = img[p + 1];
        const float4 v2 = img[p + 2];
        const float4 v3 = img[p + 3];
        const float d0 = v0.w, d1 = v1.w, d2 = v2.w, d3 = v3.w;

        // pitch: warp-uniform, one MUFU per iteration.
        const float sp = __sinf(PITCH_A - (float)i * PITCH_B);

        // 12 output floats = 48 contiguous bytes -> 3x STG.128.
        float4 o0, o1, o2;
        o0.x = d0 * c0;   o0.y = -d0 * s0;  o0.z = d0 * sp;
        o0.w = d1 * c1;
        o1.x = -d1 * s1;  o1.y = d1 * sp;
        o1.z = d2 * c2;   o1.w = -d2 * s2;
        o2.x = d2 * sp;
        o2.y = d3 * c3;   o2.z = -d3 * s3;  o2.w = d3 * sp;

        float4* outv = reinterpret_cast<float4*>(out) + (size_t)(t + k * NT) * 3;
        outv[0] = o0;
        outv[1] = o1;
        outv[2] = o2;
    }
}

extern "C" void kernel_launch(void* const* d_in, const int* in_sizes, int n_in,
                              void* d_out, int out_size) {
    const float4* img = (const float4*)d_in[0];
    float* out = (float*)d_out;

    project_persist<<<GRID, BLOCK>>>(img, out);
}

// round 12
// speedup vs baseline: 1.3275x; 1.3275x over previous
#include <cuda_runtime.h>

// ProjectionSimToPointCloud: image (2048, 8192, 4) f32 -> points (2048*8192, 3) f32
//   depth = image[..., 3]
//   pitch(i) = (1 - i/h) * (FOV_UP + |FOV_DOWN|) - |FOV_DOWN|
//   yaw(j)   = j/w * 2*pi - pi
//   x = depth*cos(yaw), y = -depth*sin(yaw), z = depth*sin(pitch)
//
// FINAL (R10 structure — measured optimum: 68.5us kernel, DRAM 77.6%,
// 6153 GB/s on a ~460MB irreducible mixed read/write stream):
//  - single fused kernel, flat grid, PPT=4
//  - 4x fully-coalesced LDG.128 front-batched (MLP=4; warp covers 2KB
//    contiguous input -> minimal L1 wavefronts)
//  - 3x fully-coalesced STG.128 (warp covers 1.5KB contiguous output)
//  - inline MUFU trig, fully hidden under the DRAM-bound window
// Falsified alternatives: scalar 64B-stride loads (L1-heavy), PPT=8
// (wavefront amplification, 87.7us), __ldcs/__stcs (sector refetch),
// L2::256B promotion (8x L2-fill amplification, 101us), persistent
// grid-stride (wave starvation, 93.2us), separate trig-table kernel
// (launch overhead). DRAM% pins at 76-78% across all instruction mixes:
// mixed R/W controller-efficiency ceiling.

#define IMG_H 2048
#define IMG_W 8192
#define PPT   4   // pixels per thread

__global__ void __launch_bounds__(256) project_fused_v4(
    const float4* __restrict__ img,   // (H*W) float4 pixels, .w = depth
    float* __restrict__ out)          // (H*W*3) floats
{
    const int t  = blockIdx.x * blockDim.x + threadIdx.x;
    const int p0 = t * PPT;                     // first pixel (multiple of 4)
    const int j0 = p0 & (IMG_W - 1);            // row not crossed (W % 4 == 0)
    const int i  = p0 >> 13;                    // log2(IMG_W) = 13

    // 4 independent fully-coalesced 128-bit loads, front-batched (MLP=4).
    const float4 v0 = img[p0 + 0];
    const float4 v1 = img[p0 + 1];
    const float4 v2 = img[p0 + 2];
    const float4 v3 = img[p0 + 3];
    const float d0 = v0.w, d1 = v1.w, d2 = v2.w, d3 = v3.w;

    // yaw(j) = j * (2*pi/W) - pi
    const float YAW_STEP = 7.6699039394282161e-4f;   // 2*pi/8192
    const float PI_F     = 3.14159265358979323846f;
    const float yaw0 = (float)j0 * YAW_STEP - PI_F;

    float s0, c0, s1, c1, s2, c2, s3, c3;
    __sincosf(yaw0,                  &s0, &c0);
    __sincosf(yaw0 + 1.f * YAW_STEP, &s1, &c1);
    __sincosf(yaw0 + 2.f * YAW_STEP, &s2, &c2);
    __sincosf(yaw0 + 3.f * YAW_STEP, &s3, &c3);

    // pitch(i) = FOV_UP - i * (span/H); warp-uniform.
    const float PITCH_A = 0.26179938779914943654f;   // FOV_UP in radians
    const float PITCH_B = 2.5566346454293863e-4f;    // (30deg in rad)/2048
    const float sp = __sinf(PITCH_A - (float)i * PITCH_B);

    // 12 output floats = 48 contiguous bytes, 16B-aligned -> 3x STG.128.
    float4 o0, o1, o2;
    o0.x = d0 * c0;   o0.y = -d0 * s0;  o0.z = d0 * sp;
    o0.w = d1 * c1;
    o1.x = -d1 * s1;  o1.y = d1 * sp;
    o1.z = d2 * c2;   o1.w = -d2 * s2;
    o2.x = d2 * sp;
    o2.y = d3 * c3;   o2.z = -d3 * s3;  o2.w = d3 * sp;

    float4* outv = reinterpret_cast<float4*>(out) + t * 3;
    outv[0] = o0;
    outv[1] = o1;
    outv[2] = o2;
}

extern "C" void kernel_launch(void* const* d_in, const int* in_sizes, int n_in,
                              void* d_out, int out_size) {
    const float4* img = (const float4*)d_in[0];
    float* out = (float*)d_out;

    const int n_threads = (IMG_H * IMG_W) / PPT;   // 4,194,304
    project_fused_v4<<<n_threads / 256, 256>>>(img, out);
}

// round 15
// speedup vs baseline: 1.3698x; 1.0319x over previous
#include <cuda_runtime.h>

// ProjectionSimToPointCloud: image (2048, 8192, 4) f32 -> points (2048*8192, 3) f32
//   depth = image[..., 3]
//   pitch(i) = (1 - i/h) * (FOV_UP + |FOV_DOWN|) - |FOV_DOWN|
//   yaw(j)   = j/w * 2*pi - pi
//   x = depth*cos(yaw), y = -depth*sin(yaw), z = depth*sin(pitch)
//
// R10 structure (measured optimum: 68.5-68.6us kernel, DRAM 77.4-77.6%,
// ~6.15 TB/s on a ~460MB irreducible mixed R/W stream), with ONE knob
// changed: block 256 -> 128 (32768 CTAs). Rationale: CTA churn empirically
// helps stream interleave (persistent-grid R11 regressed badly); finer
// CTAs give finer wave quantization + more frequent warp rotation.
// (R13 was an infra failure — this is the unmodified resubmission of the
// R12 experiment so the result stays attributable to the block-size knob.)
//  - 4x fully-coalesced LDG.128 front-batched (MLP=4)
//  - 3x STG.128 contiguous per thread
//  - inline MUFU trig, hidden under the DRAM-bound window
// Falsified: scalar loads, PPT=8, __ldcs/__stcs, L2::256B, persistent
// grid, trig-table prekernel. DRAM pins at 76-78% = controller ceiling.

#define IMG_H 2048
#define IMG_W 8192
#define PPT   4     // pixels per thread
#define BLOCK 128

__global__ void __launch_bounds__(BLOCK) project_fused_v4(
    const float4* __restrict__ img,   // (H*W) float4 pixels, .w = depth
    float* __restrict__ out)          // (H*W*3) floats
{
    const int t  = blockIdx.x * blockDim.x + threadIdx.x;
    const int p0 = t * PPT;                     // first pixel (multiple of 4)
    const int j0 = p0 & (IMG_W - 1);            // row not crossed (W % 4 == 0)
    const int i  = p0 >> 13;                    // log2(IMG_W) = 13

    // 4 independent fully-coalesced 128-bit loads, front-batched (MLP=4).
    const float4 v0 = img[p0 + 0];
    const float4 v1 = img[p0 + 1];
    const float4 v2 = img[p0 + 2];
    const float4 v3 = img[p0 + 3];
    const float d0 = v0.w, d1 = v1.w, d2 = v2.w, d3 = v3.w;

    // yaw(j) = j * (2*pi/W) - pi
    const float YAW_STEP = 7.6699039394282161e-4f;   // 2*pi/8192
    const float PI_F     = 3.14159265358979323846f;
    const float yaw0 = (float)j0 * YAW_STEP - PI_F;

    float s0, c0, s1, c1, s2, c2, s3, c3;
    __sincosf(yaw0,                  &s0, &c0);
    __sincosf(yaw0 + 1.f * YAW_STEP, &s1, &c1);
    __sincosf(yaw0 + 2.f * YAW_STEP, &s2, &c2);
    __sincosf(yaw0 + 3.f * YAW_STEP, &s3, &c3);

    // pitch(i) = FOV_UP - i * (span/H); warp-uniform.
    const float PITCH_A = 0.26179938779914943654f;   // FOV_UP in radians
    const float PITCH_B = 2.5566346454293863e-4f;    // (30deg in rad)/2048
    const float sp = __sinf(PITCH_A - (float)i * PITCH_B);

    // 12 output floats = 48 contiguous bytes, 16B-aligned -> 3x STG.128.
    float4 o0, o1, o2;
    o0.x = d0 * c0;   o0.y = -d0 * s0;  o0.z = d0 * sp;
    o0.w = d1 * c1;
    o1.x = -d1 * s1;  o1.y = d1 * sp;
    o1.z = d2 * c2;   o1.w = -d2 * s2;
    o2.x = d2 * sp;
    o2.y = d3 * c3;   o2.z = -d3 * s3;  o2.w = d3 * sp;

    float4* outv = reinterpret_cast<float4*>(out) + t * 3;
    outv[0] = o0;
    outv[1] = o1;
    outv[2] = o2;
}

extern "C" void kernel_launch(void* const* d_in, const int* in_sizes, int n_in,
                              void* d_out, int out_size) {
    const float4* img = (const float4*)d_in[0];
    float* out = (float*)d_out;

    const int n_threads = (IMG_H * IMG_W) / PPT;   // 4,194,304
    project_fused_v4<<<n_threads / BLOCK, BLOCK>>>(img, out);
}